// round 1
// baseline (speedup 1.0000x reference)
#include <cuda_runtime.h>

#define NN 50000
#define NE 800000
#define DIM 128
#define NR 8

// Scratch (device globals: allocation-free, graph-capture safe)
__device__ float g_S[(size_t)NN * NR * DIM];     // 204.8 MB aggregation buffer
__device__ float g_h[(size_t)NN * DIM];          // 25.6 MB layer-1 output
__device__ float g_W1[NR * DIM * DIM];           // composed weights layer 1
__device__ float g_W2[NR * DIM * DIM];           // composed weights layer 2

// W[r,i,o] = sum_b comp[r,b] * V[b,i,o]
__global__ void compute_W(const float* __restrict__ comp, const float* __restrict__ V,
                          float* __restrict__ W) {
    int idx = blockIdx.x * blockDim.x + threadIdx.x;   // NR*DIM*DIM = 131072
    int r  = idx >> 14;
    int io = idx & 16383;
    float acc = 0.f;
#pragma unroll
    for (int b = 0; b < NR; b++)
        acc += comp[r * NR + b] * V[b * DIM * DIM + io];
    W[idx] = acc;
}

__global__ void zero_S() {
    size_t i = (size_t)blockIdx.x * blockDim.x + threadIdx.x;   // 12.8M float4
    ((float4*)g_S)[i] = make_float4(0.f, 0.f, 0.f, 0.f);
}

// One warp per edge: lane l handles float4 chunk l of the 128-float feature row.
// S[dst, etype, :] += w * x[src, :]   via vectorized global reduction.
__global__ void scatter(const float4* __restrict__ x, const int* __restrict__ src,
                        const int* __restrict__ dst, const int* __restrict__ et,
                        const float* __restrict__ w) {
    unsigned t = blockIdx.x * blockDim.x + threadIdx.x;
    unsigned e = t >> 5;
    if (e >= NE) return;
    int lane = t & 31;
    int s = __ldg(&src[e]);
    int d = __ldg(&dst[e]);
    int r = __ldg(&et[e]);
    float we = __ldg(&w[e]);
    float4 v = x[(size_t)s * 32 + lane];
    float* p = g_S + ((size_t)d * NR + r) * DIM + lane * 4;
    asm volatile("red.global.add.v4.f32 [%0], {%1, %2, %3, %4};"
                 :: "l"(p), "f"(v.x * we), "f"(v.y * we), "f"(v.z * we), "f"(v.w * we)
                 : "memory");
}

// C[m, 0:128] = g_S[m, 0:1024] @ B[0:1024, 0:128] + bias  (optional ReLU)
// BM=64, BN=128, BK=16, 256 threads, each thread computes 4x8.
template<bool RELU>
__global__ void __launch_bounds__(256) gemm(const float* __restrict__ B,
                                            const float* __restrict__ bias,
                                            float* __restrict__ C) {
    __shared__ float  As[16][64];
    __shared__ float4 Bs[16 * 32];
    const int K = NR * DIM;  // 1024
    int t  = threadIdx.x;
    int m0 = blockIdx.x * 64;
    int ty = t >> 4, tx = t & 15;
    float acc[4][8] = {};
    int arow = t >> 2;   // 0..63
    int akq  = t & 3;    // which float4 of the 16-wide k tile
    const float4* A4 = (const float4*)g_S;
    const float4* B4 = (const float4*)B;

    for (int k0 = 0; k0 < K; k0 += 16) {
        // A tile: 64 rows x 16 k, transposed into smem
        float4 a4 = make_float4(0.f, 0.f, 0.f, 0.f);
        int grow = m0 + arow;
        if (grow < NN) a4 = A4[(size_t)grow * (K / 4) + (k0 >> 2) + akq];
        As[akq * 4 + 0][arow] = a4.x;
        As[akq * 4 + 1][arow] = a4.y;
        As[akq * 4 + 2][arow] = a4.z;
        As[akq * 4 + 3][arow] = a4.w;
        // B tile: 16 k x 128 cols
#pragma unroll
        for (int u = 0; u < 2; u++) {
            int idx = t + u * 256;
            int kk = idx >> 5, cq = idx & 31;
            Bs[kk * 32 + cq] = B4[(size_t)(k0 + kk) * 32 + cq];
        }
        __syncthreads();
#pragma unroll
        for (int kk = 0; kk < 16; kk++) {
            float4 av = *(const float4*)&As[kk][ty * 4];
            float4 b0 = Bs[kk * 32 + tx * 2];
            float4 b1 = Bs[kk * 32 + tx * 2 + 1];
            float a[4] = {av.x, av.y, av.z, av.w};
            float b[8] = {b0.x, b0.y, b0.z, b0.w, b1.x, b1.y, b1.z, b1.w};
#pragma unroll
            for (int i = 0; i < 4; i++)
#pragma unroll
                for (int j = 0; j < 8; j++)
                    acc[i][j] += a[i] * b[j];
        }
        __syncthreads();
    }

    int col = tx * 8;
    float bb[8];
#pragma unroll
    for (int j = 0; j < 8; j++) bb[j] = bias[col + j];
#pragma unroll
    for (int i = 0; i < 4; i++) {
        int row = m0 + ty * 4 + i;
        if (row < NN) {
            float v[8];
#pragma unroll
            for (int j = 0; j < 8; j++) {
                v[j] = acc[i][j] + bb[j];
                if (RELU) v[j] = fmaxf(v[j], 0.f);
            }
            float4* Cp = (float4*)(C + (size_t)row * DIM + col);
            Cp[0] = make_float4(v[0], v[1], v[2], v[3]);
            Cp[1] = make_float4(v[4], v[5], v[6], v[7]);
        }
    }
}

extern "C" void kernel_launch(void* const* d_in, const int* in_sizes, int n_in,
                              void* d_out, int out_size) {
    const float* features = (const float*)d_in[0];
    const int*   etypes   = (const int*)d_in[1];
    const float* ew       = (const float*)d_in[2];
    const int*   src      = (const int*)d_in[3];
    const int*   dst      = (const int*)d_in[4];
    const float* comp1    = (const float*)d_in[5];
    const float* V1       = (const float*)d_in[6];
    const float* bias1    = (const float*)d_in[7];
    const float* comp2    = (const float*)d_in[8];
    const float* V2       = (const float*)d_in[9];
    const float* bias2    = (const float*)d_in[10];
    float* out = (float*)d_out;

    float *W1p, *W2p, *hp;
    cudaGetSymbolAddress((void**)&W1p, g_W1);
    cudaGetSymbolAddress((void**)&W2p, g_W2);
    cudaGetSymbolAddress((void**)&hp,  g_h);

    compute_W<<<512, 256>>>(comp1, V1, W1p);
    compute_W<<<512, 256>>>(comp2, V2, W2p);

    // Layer 1
    zero_S<<<50000, 256>>>();
    scatter<<<100000, 256>>>((const float4*)features, src, dst, etypes, ew);
    gemm<true><<<(NN + 63) / 64, 256>>>(W1p, bias1, hp);

    // Layer 2
    zero_S<<<50000, 256>>>();
    scatter<<<100000, 256>>>((const float4*)hp, src, dst, etypes, ew);
    gemm<false><<<(NN + 63) / 64, 256>>>(W2p, bias2, out);
}

// round 5
// speedup vs baseline: 2.1026x; 2.1026x over previous
#include <cuda_runtime.h>
#include <cuda_bf16.h>
#include <cstdint>

#define NN 50000
#define NE 800000
#define DIM 128
#define NR 8
#define KTOT (NR * DIM)   // 1024

// ---------------- scratch (device globals: allocation-free) ----------------
__device__ float g_S[(size_t)NN * KTOT];                    // 204.8 MB agg buffer
__device__ float g_h[(size_t)NN * DIM];                     // layer-1 output
__device__ __align__(16) __nv_bfloat16 g_Whi1[DIM * KTOT];  // Wt hi/lo, [N][K]
__device__ __align__(16) __nv_bfloat16 g_Wlo1[DIM * KTOT];
__device__ __align__(16) __nv_bfloat16 g_Whi2[DIM * KTOT];
__device__ __align__(16) __nv_bfloat16 g_Wlo2[DIM * KTOT];

__device__ __forceinline__ uint32_t smem_u32(const void* p) {
    uint32_t a;
    asm("{ .reg .u64 t; cvta.to.shared.u64 t, %1; cvt.u32.u64 %0, t; }" : "=r"(a) : "l"(p));
    return a;
}

// ---------------- W composition: Wt[n][k] split into bf16 hi/lo ----------------
__global__ void compute_Wt(const float* __restrict__ comp, const float* __restrict__ V,
                           __nv_bfloat16* __restrict__ Whi, __nv_bfloat16* __restrict__ Wlo) {
    int idx = blockIdx.x * blockDim.x + threadIdx.x;   // 131072
    int r = idx >> 14;
    int io = idx & 16383;
    int i = io >> 7;
    int o = io & 127;
    float acc = 0.f;
#pragma unroll
    for (int b = 0; b < NR; b++)
        acc += comp[r * NR + b] * V[b * 16384 + io];
    __nv_bfloat16 hi = __float2bfloat16(acc);
    __nv_bfloat16 lo = __float2bfloat16(acc - __bfloat162float(hi));
    int k = r * DIM + i;
    Whi[(size_t)o * KTOT + k] = hi;
    Wlo[(size_t)o * KTOT + k] = lo;
}

__global__ void zero_S() {
    size_t i = (size_t)blockIdx.x * blockDim.x + threadIdx.x;   // 12.8M float4
    ((float4*)g_S)[i] = make_float4(0.f, 0.f, 0.f, 0.f);
}

// One warp per edge: S[dst, etype, :] += w * x[src, :]
__global__ void scatter(const float4* __restrict__ x, const int* __restrict__ src,
                        const int* __restrict__ dst, const int* __restrict__ et,
                        const float* __restrict__ w) {
    unsigned t = blockIdx.x * blockDim.x + threadIdx.x;
    unsigned e = t >> 5;
    if (e >= NE) return;
    int lane = t & 31;
    int s = __ldg(&src[e]);
    int d = __ldg(&dst[e]);
    int r = __ldg(&et[e]);
    float we = __ldg(&w[e]);
    float4 v = x[(size_t)s * 32 + lane];
    float* p = g_S + ((size_t)d * NR + r) * DIM + lane * 4;
    asm volatile("red.global.add.v4.f32 [%0], {%1, %2, %3, %4};"
                 :: "l"(p), "f"(v.x * we), "f"(v.y * we), "f"(v.z * we), "f"(v.w * we)
                 : "memory");
}

// ---------------- split-bf16 HMMA GEMM ----------------
// C[m,0:128] = A[m,0:1024] @ Wt^T + bias.  BM=128, BN=128, BK=64, 256 thr.
// Warp grid 2(m) x 4(n); warp tile 64x32; mma.m16n8k16, 3 mmas (hi*hi+hi*lo+lo*hi).
#define ASTR 144            // smem row stride in bytes (72 bf16: 64 data + 8 pad)
#define SM_AHI 0
#define SM_ALO 18432
#define SM_BHI 36864
#define SM_BLO 55296
#define SM_TOT 73728

__device__ __forceinline__ void ldsm_x4(uint32_t* r, uint32_t addr) {
    asm volatile("ldmatrix.sync.aligned.m8n8.x4.shared.b16 {%0,%1,%2,%3}, [%4];"
                 : "=r"(r[0]), "=r"(r[1]), "=r"(r[2]), "=r"(r[3]) : "r"(addr));
}
__device__ __forceinline__ void mma16816(float* c, const uint32_t* a, const uint32_t* b) {
    asm volatile(
        "mma.sync.aligned.m16n8k16.row.col.f32.bf16.bf16.f32 "
        "{%0,%1,%2,%3}, {%4,%5,%6,%7}, {%8,%9}, {%0,%1,%2,%3};"
        : "+f"(c[0]), "+f"(c[1]), "+f"(c[2]), "+f"(c[3])
        : "r"(a[0]), "r"(a[1]), "r"(a[2]), "r"(a[3]), "r"(b[0]), "r"(b[1]));
}

template<bool RELU>
__global__ void __launch_bounds__(256, 2) gemm_tc(const float* __restrict__ A,
                                                  const __nv_bfloat16* __restrict__ Bhi,
                                                  const __nv_bfloat16* __restrict__ Blo,
                                                  const float* __restrict__ bias,
                                                  float* __restrict__ C) {
    extern __shared__ char dsm[];
    uint32_t sb = smem_u32(dsm);
    int t = threadIdx.x;
    int lane = t & 31, wid = t >> 5;
    int warp_m = wid >> 2, warp_n = wid & 3;
    int m0 = blockIdx.x * 128;

    float acc[4][4][4] = {};   // [mt][nt][4]

    for (int kc = 0; kc < 16; kc++) {
        // ---- B tiles via cp.async: hi then lo, 128 rows x 8 uint4 ----
#pragma unroll
        for (int j = 0; j < 8; j++) {
            int lin = t + j * 256;                 // 0..2047
            int l2 = lin & 1023;
            int row = l2 >> 3, q = l2 & 7;
            const __nv_bfloat16* srcp = (lin < 1024) ? Bhi : Blo;
            uint32_t db = sb + ((lin < 1024) ? SM_BHI : SM_BLO) + row * ASTR + q * 16;
            const void* gp = srcp + (size_t)row * KTOT + kc * 64 + q * 8;
            asm volatile("cp.async.ca.shared.global [%0], [%1], 16;"
                         :: "r"(db), "l"(gp) : "memory");
        }
        // ---- A tile: 128 rows x 64 k fp32 -> bf16 hi/lo ----
#pragma unroll
        for (int j = 0; j < 8; j++) {
            int lin = t + j * 256;
            int row = lin >> 4, q = lin & 15;      // 16 float4 per row
            float4 v = make_float4(0.f, 0.f, 0.f, 0.f);
            int gr = m0 + row;
            if (gr < NN) v = *(const float4*)(A + (size_t)gr * KTOT + kc * 64 + q * 4);
            __nv_bfloat16 hx = __float2bfloat16(v.x), hy = __float2bfloat16(v.y);
            __nv_bfloat16 hz = __float2bfloat16(v.z), hw = __float2bfloat16(v.w);
            __nv_bfloat16 lx = __float2bfloat16(v.x - __bfloat162float(hx));
            __nv_bfloat16 ly = __float2bfloat16(v.y - __bfloat162float(hy));
            __nv_bfloat16 lz = __float2bfloat16(v.z - __bfloat162float(hz));
            __nv_bfloat16 lw = __float2bfloat16(v.w - __bfloat162float(hw));
            uint32_t h01 = (uint32_t)__bfloat16_as_ushort(hx) | ((uint32_t)__bfloat16_as_ushort(hy) << 16);
            uint32_t h23 = (uint32_t)__bfloat16_as_ushort(hz) | ((uint32_t)__bfloat16_as_ushort(hw) << 16);
            uint32_t l01 = (uint32_t)__bfloat16_as_ushort(lx) | ((uint32_t)__bfloat16_as_ushort(ly) << 16);
            uint32_t l23 = (uint32_t)__bfloat16_as_ushort(lz) | ((uint32_t)__bfloat16_as_ushort(lw) << 16);
            uint32_t off = row * ASTR + q * 8;
            asm volatile("st.shared.v2.b32 [%0], {%1,%2};"
                         :: "r"(sb + SM_AHI + off), "r"(h01), "r"(h23) : "memory");
            asm volatile("st.shared.v2.b32 [%0], {%1,%2};"
                         :: "r"(sb + SM_ALO + off), "r"(l01), "r"(l23) : "memory");
        }
        asm volatile("cp.async.commit_group;\n\tcp.async.wait_group 0;" ::: "memory");
        __syncthreads();

        // ---- MMA: 4 k16-steps ----
#pragma unroll
        for (int ks = 0; ks < 4; ks++) {
            // B frags: n = warp_n*32 + pair*16 + (lane>=16)*8 + lane%8,
            //          byte = ks*32 + ((lane>>3)&1)*16
            uint32_t bhi[2][4], blo[2][4];
            int brow = warp_n * 32 + ((lane >> 4) & 1) * 8 + (lane & 7);
            uint32_t bcol = ks * 32 + ((lane >> 3) & 1) * 16;
#pragma unroll
            for (int pr = 0; pr < 2; pr++) {
                uint32_t boff = (brow + pr * 16) * ASTR + bcol;
                ldsm_x4(bhi[pr], sb + SM_BHI + boff);
                ldsm_x4(blo[pr], sb + SM_BLO + boff);
            }
#pragma unroll
            for (int mt = 0; mt < 4; mt++) {
                uint32_t ahi[4], alo[4];
                int arow = warp_m * 64 + mt * 16 + (lane & 15);
                uint32_t aoff = arow * ASTR + ks * 32 + (lane >> 4) * 16;
                ldsm_x4(ahi, sb + SM_AHI + aoff);
                ldsm_x4(alo, sb + SM_ALO + aoff);
#pragma unroll
                for (int nt = 0; nt < 4; nt++) {
                    const uint32_t* bh = &bhi[nt >> 1][(nt & 1) * 2];
                    const uint32_t* bl = &blo[nt >> 1][(nt & 1) * 2];
                    mma16816(acc[mt][nt], ahi, bh);
                    mma16816(acc[mt][nt], ahi, bl);
                    mma16816(acc[mt][nt], alo, bh);
                }
            }
        }
        __syncthreads();
    }

    // ---- epilogue ----
    int group = lane >> 2, tig = lane & 3;
#pragma unroll
    for (int mt = 0; mt < 4; mt++) {
#pragma unroll
        for (int half = 0; half < 2; half++) {
            int row = m0 + warp_m * 64 + mt * 16 + group + half * 8;
            if (row < NN) {
#pragma unroll
                for (int nt = 0; nt < 4; nt++) {
                    int col = warp_n * 32 + nt * 8 + 2 * tig;
                    float v0 = acc[mt][nt][half * 2 + 0] + bias[col];
                    float v1 = acc[mt][nt][half * 2 + 1] + bias[col + 1];
                    if (RELU) { v0 = fmaxf(v0, 0.f); v1 = fmaxf(v1, 0.f); }
                    *(float2*)(C + (size_t)row * DIM + col) = make_float2(v0, v1);
                }
            }
        }
    }
}

// ---------------- launch ----------------
extern "C" void kernel_launch(void* const* d_in, const int* in_sizes, int n_in,
                              void* d_out, int out_size) {
    const float* features = (const float*)d_in[0];
    const int*   etypes   = (const int*)d_in[1];
    const float* ew       = (const float*)d_in[2];
    const int*   src      = (const int*)d_in[3];
    const int*   dst      = (const int*)d_in[4];
    const float* comp1    = (const float*)d_in[5];
    const float* V1       = (const float*)d_in[6];
    const float* bias1    = (const float*)d_in[7];
    const float* comp2    = (const float*)d_in[8];
    const float* V2       = (const float*)d_in[9];
    const float* bias2    = (const float*)d_in[10];
    float* out = (float*)d_out;

    float *Sp, *hp;
    __nv_bfloat16 *Whi1, *Wlo1, *Whi2, *Wlo2;
    cudaGetSymbolAddress((void**)&Sp,   g_S);
    cudaGetSymbolAddress((void**)&hp,   g_h);
    cudaGetSymbolAddress((void**)&Whi1, g_Whi1);
    cudaGetSymbolAddress((void**)&Wlo1, g_Wlo1);
    cudaGetSymbolAddress((void**)&Whi2, g_Whi2);
    cudaGetSymbolAddress((void**)&Wlo2, g_Wlo2);

    cudaFuncSetAttribute(gemm_tc<true>,  cudaFuncAttributeMaxDynamicSharedMemorySize, SM_TOT);
    cudaFuncSetAttribute(gemm_tc<false>, cudaFuncAttributeMaxDynamicSharedMemorySize, SM_TOT);

    compute_Wt<<<512, 256>>>(comp1, V1, Whi1, Wlo1);
    compute_Wt<<<512, 256>>>(comp2, V2, Whi2, Wlo2);

    const int GEMM_GRID = (NN + 127) / 128;   // 391

    // Layer 1
    zero_S<<<50000, 256>>>();
    scatter<<<100000, 256>>>((const float4*)features, src, dst, etypes, ew);
    gemm_tc<true><<<GEMM_GRID, 256, SM_TOT>>>(Sp, Whi1, Wlo1, bias1, hp);

    // Layer 2
    zero_S<<<50000, 256>>>();
    scatter<<<100000, 256>>>((const float4*)hp, src, dst, etypes, ew);
    gemm_tc<false><<<GEMM_GRID, 256, SM_TOT>>>(Sp, Whi2, Wlo2, bias2, out);
}

// round 6
// speedup vs baseline: 2.5778x; 1.2260x over previous
#include <cuda_runtime.h>
#include <cuda_bf16.h>
#include <cstdint>

#define NN 50000
#define NE 800000
#define DIM 128
#define NR 8
#define NOUT (NR * DIM)   // 1024 = Y row length

// ---------------- scratch (device globals: allocation-free) ----------------
__device__ float g_Y[(size_t)NN * NOUT];                   // 204.8 MB projected features
__device__ float g_h[(size_t)NN * DIM];                    // layer-1 output
__device__ __align__(16) __nv_bfloat16 g_Whi1[NOUT * DIM]; // Wt hi/lo, [n=r*128+o][k=i]
__device__ __align__(16) __nv_bfloat16 g_Wlo1[NOUT * DIM];
__device__ __align__(16) __nv_bfloat16 g_Whi2[NOUT * DIM];
__device__ __align__(16) __nv_bfloat16 g_Wlo2[NOUT * DIM];

__device__ __forceinline__ uint32_t smem_u32(const void* p) {
    uint32_t a;
    asm("{ .reg .u64 t; cvta.to.shared.u64 t, %1; cvt.u32.u64 %0, t; }" : "=r"(a) : "l"(p));
    return a;
}

// ---------------- W composition: Wt[n][k] split into bf16 hi/lo ----------------
// Wt[(r*128+o)][i] = sum_b comp[r,b] * V[b, i, o]
__global__ void compute_Wt(const float* __restrict__ comp, const float* __restrict__ V,
                           __nv_bfloat16* __restrict__ Whi, __nv_bfloat16* __restrict__ Wlo) {
    int idx = blockIdx.x * blockDim.x + threadIdx.x;   // 131072
    int r = idx >> 14;
    int io = idx & 16383;
    int i = io >> 7;
    int o = io & 127;
    float acc = 0.f;
#pragma unroll
    for (int b = 0; b < NR; b++)
        acc += comp[r * NR + b] * V[b * 16384 + io];
    __nv_bfloat16 hi = __float2bfloat16(acc);
    __nv_bfloat16 lo = __float2bfloat16(acc - __bfloat162float(hi));
    int n = r * DIM + o;
    Whi[(size_t)n * DIM + i] = hi;
    Wlo[(size_t)n * DIM + i] = lo;
}

// dst[n, c] = bias[c]  for all n  (out buffer pre-init; scatter accumulates on top)
__global__ void init_bias(float4* __restrict__ dst, const float4* __restrict__ bias) {
    int idx = blockIdx.x * blockDim.x + threadIdx.x;   // NN*32 = 1.6M float4
    dst[idx] = bias[idx & 31];
}

// One warp per edge: out[dst, :] += w * Y[src, rel, :]
__global__ void scatter_out(const float4* __restrict__ Y, const int* __restrict__ src,
                            const int* __restrict__ dst, const int* __restrict__ et,
                            const float* __restrict__ w, float* __restrict__ out) {
    unsigned t = blockIdx.x * blockDim.x + threadIdx.x;
    unsigned e = t >> 5;
    if (e >= NE) return;
    int lane = t & 31;
    int s = __ldg(&src[e]);
    int d = __ldg(&dst[e]);
    int r = __ldg(&et[e]);
    float we = __ldg(&w[e]);
    float4 v = Y[(size_t)s * (NOUT / 4) + r * 32 + lane];
    float* p = out + (size_t)d * DIM + lane * 4;
    asm volatile("red.global.add.v4.f32 [%0], {%1, %2, %3, %4};"
                 :: "l"(p), "f"(v.x * we), "f"(v.y * we), "f"(v.z * we), "f"(v.w * we)
                 : "memory");
}

// ---------------- split-bf16 HMMA GEMM: Y = X @ Wt^T ----------------
// M=50000, N=1024, K=128. BM=128, BN=128, BK=64 (2 k-iters), 256 thr.
// Warp grid 2(m) x 4(n); warp tile 64x32; mma.m16n8k16; 3 mmas (hi*hi+hi*lo+lo*hi).
// RELU_A applies relu to A on load (layer-2 input = pre-activation h).
#define ASTR 144            // smem row stride bytes (72 bf16: 64 data + 8 pad)
#define SM_AHI 0
#define SM_ALO 18432
#define SM_BHI 36864
#define SM_BLO 55296
#define SM_TOT 73728

__device__ __forceinline__ void ldsm_x4(uint32_t* r, uint32_t addr) {
    asm volatile("ldmatrix.sync.aligned.m8n8.x4.shared.b16 {%0,%1,%2,%3}, [%4];"
                 : "=r"(r[0]), "=r"(r[1]), "=r"(r[2]), "=r"(r[3]) : "r"(addr));
}
__device__ __forceinline__ void mma16816(float* c, const uint32_t* a, const uint32_t* b) {
    asm volatile(
        "mma.sync.aligned.m16n8k16.row.col.f32.bf16.bf16.f32 "
        "{%0,%1,%2,%3}, {%4,%5,%6,%7}, {%8,%9}, {%0,%1,%2,%3};"
        : "+f"(c[0]), "+f"(c[1]), "+f"(c[2]), "+f"(c[3])
        : "r"(a[0]), "r"(a[1]), "r"(a[2]), "r"(a[3]), "r"(b[0]), "r"(b[1]));
}

template<bool RELU_A>
__global__ void __launch_bounds__(256, 2) gemm_y(const float* __restrict__ A,
                                                 const __nv_bfloat16* __restrict__ Bhi,
                                                 const __nv_bfloat16* __restrict__ Blo,
                                                 float* __restrict__ Y) {
    extern __shared__ char dsm[];
    uint32_t sb = smem_u32(dsm);
    int t = threadIdx.x;
    int lane = t & 31, wid = t >> 5;
    int warp_m = wid >> 2, warp_n = wid & 3;
    int m0 = blockIdx.x * 128;
    int n0 = blockIdx.y * 128;

    float acc[4][4][4] = {};   // [mt][nt][4]

    for (int kc = 0; kc < 2; kc++) {
        // ---- B tiles via cp.async: hi then lo, 128 n-rows x 64 k ----
#pragma unroll
        for (int j = 0; j < 8; j++) {
            int lin = t + j * 256;                 // 0..2047
            int l2 = lin & 1023;
            int row = l2 >> 3, q = l2 & 7;
            const __nv_bfloat16* srcp = (lin < 1024) ? Bhi : Blo;
            uint32_t db = sb + ((lin < 1024) ? SM_BHI : SM_BLO) + row * ASTR + q * 16;
            const void* gp = srcp + (size_t)(n0 + row) * DIM + kc * 64 + q * 8;
            asm volatile("cp.async.ca.shared.global [%0], [%1], 16;"
                         :: "r"(db), "l"(gp) : "memory");
        }
        // ---- A tile: 128 rows x 64 k fp32 -> (relu) -> bf16 hi/lo ----
#pragma unroll
        for (int j = 0; j < 8; j++) {
            int lin = t + j * 256;
            int row = lin >> 4, q = lin & 15;      // 16 float4 per row
            float4 v = make_float4(0.f, 0.f, 0.f, 0.f);
            int gr = m0 + row;
            if (gr < NN) v = *(const float4*)(A + (size_t)gr * DIM + kc * 64 + q * 4);
            if (RELU_A) {
                v.x = fmaxf(v.x, 0.f); v.y = fmaxf(v.y, 0.f);
                v.z = fmaxf(v.z, 0.f); v.w = fmaxf(v.w, 0.f);
            }
            __nv_bfloat16 hx = __float2bfloat16(v.x), hy = __float2bfloat16(v.y);
            __nv_bfloat16 hz = __float2bfloat16(v.z), hw = __float2bfloat16(v.w);
            __nv_bfloat16 lx = __float2bfloat16(v.x - __bfloat162float(hx));
            __nv_bfloat16 ly = __float2bfloat16(v.y - __bfloat162float(hy));
            __nv_bfloat16 lz = __float2bfloat16(v.z - __bfloat162float(hz));
            __nv_bfloat16 lw = __float2bfloat16(v.w - __bfloat162float(hw));
            uint32_t h01 = (uint32_t)__bfloat16_as_ushort(hx) | ((uint32_t)__bfloat16_as_ushort(hy) << 16);
            uint32_t h23 = (uint32_t)__bfloat16_as_ushort(hz) | ((uint32_t)__bfloat16_as_ushort(hw) << 16);
            uint32_t l01 = (uint32_t)__bfloat16_as_ushort(lx) | ((uint32_t)__bfloat16_as_ushort(ly) << 16);
            uint32_t l23 = (uint32_t)__bfloat16_as_ushort(lz) | ((uint32_t)__bfloat16_as_ushort(lw) << 16);
            uint32_t off = row * ASTR + q * 8;
            asm volatile("st.shared.v2.b32 [%0], {%1,%2};"
                         :: "r"(sb + SM_AHI + off), "r"(h01), "r"(h23) : "memory");
            asm volatile("st.shared.v2.b32 [%0], {%1,%2};"
                         :: "r"(sb + SM_ALO + off), "r"(l01), "r"(l23) : "memory");
        }
        asm volatile("cp.async.commit_group;\n\tcp.async.wait_group 0;" ::: "memory");
        __syncthreads();

        // ---- MMA: 4 k16-steps ----
#pragma unroll
        for (int ks = 0; ks < 4; ks++) {
            uint32_t bhi[2][4], blo[2][4];
            int brow = warp_n * 32 + ((lane >> 4) & 1) * 8 + (lane & 7);
            uint32_t bcol = ks * 32 + ((lane >> 3) & 1) * 16;
#pragma unroll
            for (int pr = 0; pr < 2; pr++) {
                uint32_t boff = (brow + pr * 16) * ASTR + bcol;
                ldsm_x4(bhi[pr], sb + SM_BHI + boff);
                ldsm_x4(blo[pr], sb + SM_BLO + boff);
            }
#pragma unroll
            for (int mt = 0; mt < 4; mt++) {
                uint32_t ahi[4], alo[4];
                int arow = warp_m * 64 + mt * 16 + (lane & 15);
                uint32_t aoff = arow * ASTR + ks * 32 + (lane >> 4) * 16;
                ldsm_x4(ahi, sb + SM_AHI + aoff);
                ldsm_x4(alo, sb + SM_ALO + aoff);
#pragma unroll
                for (int nt = 0; nt < 4; nt++) {
                    const uint32_t* bh = &bhi[nt >> 1][(nt & 1) * 2];
                    const uint32_t* bl = &blo[nt >> 1][(nt & 1) * 2];
                    mma16816(acc[mt][nt], ahi, bh);
                    mma16816(acc[mt][nt], ahi, bl);
                    mma16816(acc[mt][nt], alo, bh);
                }
            }
        }
        __syncthreads();
    }

    // ---- epilogue: raw Y (bias/relu handled elsewhere) ----
    int group = lane >> 2, tig = lane & 3;
#pragma unroll
    for (int mt = 0; mt < 4; mt++) {
#pragma unroll
        for (int half = 0; half < 2; half++) {
            int row = m0 + warp_m * 64 + mt * 16 + group + half * 8;
            if (row < NN) {
#pragma unroll
                for (int nt = 0; nt < 4; nt++) {
                    int col = n0 + warp_n * 32 + nt * 8 + 2 * tig;
                    *(float2*)(Y + (size_t)row * NOUT + col) =
                        make_float2(acc[mt][nt][half * 2 + 0], acc[mt][nt][half * 2 + 1]);
                }
            }
        }
    }
}

// ---------------- launch ----------------
extern "C" void kernel_launch(void* const* d_in, const int* in_sizes, int n_in,
                              void* d_out, int out_size) {
    const float* features = (const float*)d_in[0];
    const int*   etypes   = (const int*)d_in[1];
    const float* ew       = (const float*)d_in[2];
    const int*   src      = (const int*)d_in[3];
    const int*   dst      = (const int*)d_in[4];
    const float* comp1    = (const float*)d_in[5];
    const float* V1       = (const float*)d_in[6];
    const float* bias1    = (const float*)d_in[7];
    const float* comp2    = (const float*)d_in[8];
    const float* V2       = (const float*)d_in[9];
    const float* bias2    = (const float*)d_in[10];
    float* out = (float*)d_out;

    float *Yp, *hp;
    __nv_bfloat16 *Whi1, *Wlo1, *Whi2, *Wlo2;
    cudaGetSymbolAddress((void**)&Yp,   g_Y);
    cudaGetSymbolAddress((void**)&hp,   g_h);
    cudaGetSymbolAddress((void**)&Whi1, g_Whi1);
    cudaGetSymbolAddress((void**)&Wlo1, g_Wlo1);
    cudaGetSymbolAddress((void**)&Whi2, g_Whi2);
    cudaGetSymbolAddress((void**)&Wlo2, g_Wlo2);

    cudaFuncSetAttribute(gemm_y<false>, cudaFuncAttributeMaxDynamicSharedMemorySize, SM_TOT);
    cudaFuncSetAttribute(gemm_y<true>,  cudaFuncAttributeMaxDynamicSharedMemorySize, SM_TOT);

    compute_Wt<<<512, 256>>>(comp1, V1, Whi1, Wlo1);
    compute_Wt<<<512, 256>>>(comp2, V2, Whi2, Wlo2);

    dim3 ggrid((NN + 127) / 128, NR);   // 391 x 8

    // Layer 1: Y = X @ W1 ; h = bias1 + scatter(Y)
    gemm_y<false><<<ggrid, 256, SM_TOT>>>(features, Whi1, Wlo1, Yp);
    init_bias<<<NN * 32 / 256, 256>>>((float4*)hp, (const float4*)bias1);
    scatter_out<<<100000, 256>>>((const float4*)Yp, src, dst, etypes, ew, hp);

    // Layer 2: Y = relu(h) @ W2 ; out = bias2 + scatter(Y)
    gemm_y<true><<<ggrid, 256, SM_TOT>>>(hp, Whi2, Wlo2, Yp);
    init_bias<<<NN * 32 / 256, 256>>>((float4*)out, (const float4*)bias2);
    scatter_out<<<100000, 256>>>((const float4*)Yp, src, dst, etypes, ew, out);
}

// round 7
// speedup vs baseline: 2.7069x; 1.0501x over previous
#include <cuda_runtime.h>
#include <cuda_bf16.h>
#include <cuda_fp16.h>
#include <cstdint>

#define NN 50000
#define NE 800000
#define DIM 128
#define NR 8
#define NOUT (NR * DIM)   // 1024 = Y row length

// ---------------- scratch (device globals: allocation-free) ----------------
__device__ __align__(16) __half g_Y[(size_t)NN * NOUT];    // 102.4 MB projected features (fp16)
__device__ float g_h[(size_t)NN * DIM];                    // layer-1 output (fp32)
__device__ __align__(16) __nv_bfloat16 g_Whi1[NOUT * DIM]; // Wt hi/lo, [n=r*128+o][k=i]
__device__ __align__(16) __nv_bfloat16 g_Wlo1[NOUT * DIM];
__device__ __align__(16) __nv_bfloat16 g_Whi2[NOUT * DIM];
__device__ __align__(16) __nv_bfloat16 g_Wlo2[NOUT * DIM];

__device__ __forceinline__ uint32_t smem_u32(const void* p) {
    uint32_t a;
    asm("{ .reg .u64 t; cvta.to.shared.u64 t, %1; cvt.u32.u64 %0, t; }" : "=r"(a) : "l"(p));
    return a;
}

// ---------------- W composition: Wt[n][k] split into bf16 hi/lo ----------------
// Wt[(r*128+o)][i] = sum_b comp[r,b] * V[b, i, o]
__global__ void compute_Wt(const float* __restrict__ comp, const float* __restrict__ V,
                           __nv_bfloat16* __restrict__ Whi, __nv_bfloat16* __restrict__ Wlo) {
    int idx = blockIdx.x * blockDim.x + threadIdx.x;   // 131072
    int r = idx >> 14;
    int io = idx & 16383;
    int i = io >> 7;
    int o = io & 127;
    float acc = 0.f;
#pragma unroll
    for (int b = 0; b < NR; b++)
        acc += comp[r * NR + b] * V[b * 16384 + io];
    __nv_bfloat16 hi = __float2bfloat16(acc);
    __nv_bfloat16 lo = __float2bfloat16(acc - __bfloat162float(hi));
    int n = r * DIM + o;
    Whi[(size_t)n * DIM + i] = hi;
    Wlo[(size_t)n * DIM + i] = lo;
}

// dst[n, c] = bias[c]  for all n  (out buffer pre-init; scatter accumulates on top)
__global__ void init_bias(float4* __restrict__ dst, const float4* __restrict__ bias) {
    int idx = blockIdx.x * blockDim.x + threadIdx.x;   // NN*32 = 1.6M float4
    dst[idx] = bias[idx & 31];
}

// 16 lanes per edge (2 edges/warp): out[dst, :] += w * Y[src, rel, :]
// Lane j loads uint4 = 8 halves of the 128-half Y slice.
__global__ void scatter_out(const uint4* __restrict__ Y, const int* __restrict__ src,
                            const int* __restrict__ dst, const int* __restrict__ et,
                            const float* __restrict__ w, float* __restrict__ out) {
    unsigned t = blockIdx.x * blockDim.x + threadIdx.x;
    unsigned e = t >> 4;
    if (e >= NE) return;
    int lane = t & 15;
    int s = __ldg(&src[e]);
    int d = __ldg(&dst[e]);
    int r = __ldg(&et[e]);
    float we = __ldg(&w[e]);
    // Y row = 1024 halves = 128 uint4; rel block = 16 uint4
    uint4 v = Y[(size_t)s * 128 + r * 16 + lane];
    float2 f0 = __half22float2(*(const __half2*)&v.x);
    float2 f1 = __half22float2(*(const __half2*)&v.y);
    float2 f2 = __half22float2(*(const __half2*)&v.z);
    float2 f3 = __half22float2(*(const __half2*)&v.w);
    float* p = out + (size_t)d * DIM + lane * 8;
    asm volatile("red.global.add.v4.f32 [%0], {%1, %2, %3, %4};"
                 :: "l"(p), "f"(f0.x * we), "f"(f0.y * we), "f"(f1.x * we), "f"(f1.y * we)
                 : "memory");
    asm volatile("red.global.add.v4.f32 [%0], {%1, %2, %3, %4};"
                 :: "l"(p + 4), "f"(f2.x * we), "f"(f2.y * we), "f"(f3.x * we), "f"(f3.y * we)
                 : "memory");
}

// ---------------- split-bf16 HMMA GEMM: Y = X @ Wt^T (fp16 out) ----------------
// M=50000, N=1024, K=128. BM=128, BN=128, BK=64 (2 k-iters), 256 thr.
// Warp grid 2(m) x 4(n); warp tile 64x32; mma.m16n8k16; 3 mmas (hi*hi+hi*lo+lo*hi).
#define ASTR 144            // smem row stride bytes (72 bf16: 64 data + 8 pad)
#define SM_AHI 0
#define SM_ALO 18432
#define SM_BHI 36864
#define SM_BLO 55296
#define SM_TOT 73728

__device__ __forceinline__ void ldsm_x4(uint32_t* r, uint32_t addr) {
    asm volatile("ldmatrix.sync.aligned.m8n8.x4.shared.b16 {%0,%1,%2,%3}, [%4];"
                 : "=r"(r[0]), "=r"(r[1]), "=r"(r[2]), "=r"(r[3]) : "r"(addr));
}
__device__ __forceinline__ void mma16816(float* c, const uint32_t* a, const uint32_t* b) {
    asm volatile(
        "mma.sync.aligned.m16n8k16.row.col.f32.bf16.bf16.f32 "
        "{%0,%1,%2,%3}, {%4,%5,%6,%7}, {%8,%9}, {%0,%1,%2,%3};"
        : "+f"(c[0]), "+f"(c[1]), "+f"(c[2]), "+f"(c[3])
        : "r"(a[0]), "r"(a[1]), "r"(a[2]), "r"(a[3]), "r"(b[0]), "r"(b[1]));
}

template<bool RELU_A>
__global__ void __launch_bounds__(256, 2) gemm_y(const float* __restrict__ A,
                                                 const __nv_bfloat16* __restrict__ Bhi,
                                                 const __nv_bfloat16* __restrict__ Blo,
                                                 __half* __restrict__ Y) {
    extern __shared__ char dsm[];
    uint32_t sb = smem_u32(dsm);
    int t = threadIdx.x;
    int lane = t & 31, wid = t >> 5;
    int warp_m = wid >> 2, warp_n = wid & 3;
    int m0 = blockIdx.x * 128;
    int n0 = blockIdx.y * 128;

    float acc[4][4][4] = {};   // [mt][nt][4]

    for (int kc = 0; kc < 2; kc++) {
        // ---- B tiles via cp.async: hi then lo, 128 n-rows x 64 k ----
#pragma unroll
        for (int j = 0; j < 8; j++) {
            int lin = t + j * 256;                 // 0..2047
            int l2 = lin & 1023;
            int row = l2 >> 3, q = l2 & 7;
            const __nv_bfloat16* srcp = (lin < 1024) ? Bhi : Blo;
            uint32_t db = sb + ((lin < 1024) ? SM_BHI : SM_BLO) + row * ASTR + q * 16;
            const void* gp = srcp + (size_t)(n0 + row) * DIM + kc * 64 + q * 8;
            asm volatile("cp.async.ca.shared.global [%0], [%1], 16;"
                         :: "r"(db), "l"(gp) : "memory");
        }
        // ---- A tile: 128 rows x 64 k fp32 -> (relu) -> bf16 hi/lo ----
#pragma unroll
        for (int j = 0; j < 8; j++) {
            int lin = t + j * 256;
            int row = lin >> 4, q = lin & 15;      // 16 float4 per row
            float4 v = make_float4(0.f, 0.f, 0.f, 0.f);
            int gr = m0 + row;
            if (gr < NN) v = *(const float4*)(A + (size_t)gr * DIM + kc * 64 + q * 4);
            if (RELU_A) {
                v.x = fmaxf(v.x, 0.f); v.y = fmaxf(v.y, 0.f);
                v.z = fmaxf(v.z, 0.f); v.w = fmaxf(v.w, 0.f);
            }
            __nv_bfloat16 hx = __float2bfloat16(v.x), hy = __float2bfloat16(v.y);
            __nv_bfloat16 hz = __float2bfloat16(v.z), hw = __float2bfloat16(v.w);
            __nv_bfloat16 lx = __float2bfloat16(v.x - __bfloat162float(hx));
            __nv_bfloat16 ly = __float2bfloat16(v.y - __bfloat162float(hy));
            __nv_bfloat16 lz = __float2bfloat16(v.z - __bfloat162float(hz));
            __nv_bfloat16 lw = __float2bfloat16(v.w - __bfloat162float(hw));
            uint32_t h01 = (uint32_t)__bfloat16_as_ushort(hx) | ((uint32_t)__bfloat16_as_ushort(hy) << 16);
            uint32_t h23 = (uint32_t)__bfloat16_as_ushort(hz) | ((uint32_t)__bfloat16_as_ushort(hw) << 16);
            uint32_t l01 = (uint32_t)__bfloat16_as_ushort(lx) | ((uint32_t)__bfloat16_as_ushort(ly) << 16);
            uint32_t l23 = (uint32_t)__bfloat16_as_ushort(lz) | ((uint32_t)__bfloat16_as_ushort(lw) << 16);
            uint32_t off = row * ASTR + q * 8;
            asm volatile("st.shared.v2.b32 [%0], {%1,%2};"
                         :: "r"(sb + SM_AHI + off), "r"(h01), "r"(h23) : "memory");
            asm volatile("st.shared.v2.b32 [%0], {%1,%2};"
                         :: "r"(sb + SM_ALO + off), "r"(l01), "r"(l23) : "memory");
        }
        asm volatile("cp.async.commit_group;\n\tcp.async.wait_group 0;" ::: "memory");
        __syncthreads();

        // ---- MMA: 4 k16-steps ----
#pragma unroll
        for (int ks = 0; ks < 4; ks++) {
            uint32_t bhi[2][4], blo[2][4];
            int brow = warp_n * 32 + ((lane >> 4) & 1) * 8 + (lane & 7);
            uint32_t bcol = ks * 32 + ((lane >> 3) & 1) * 16;
#pragma unroll
            for (int pr = 0; pr < 2; pr++) {
                uint32_t boff = (brow + pr * 16) * ASTR + bcol;
                ldsm_x4(bhi[pr], sb + SM_BHI + boff);
                ldsm_x4(blo[pr], sb + SM_BLO + boff);
            }
#pragma unroll
            for (int mt = 0; mt < 4; mt++) {
                uint32_t ahi[4], alo[4];
                int arow = warp_m * 64 + mt * 16 + (lane & 15);
                uint32_t aoff = arow * ASTR + ks * 32 + (lane >> 4) * 16;
                ldsm_x4(ahi, sb + SM_AHI + aoff);
                ldsm_x4(alo, sb + SM_ALO + aoff);
#pragma unroll
                for (int nt = 0; nt < 4; nt++) {
                    const uint32_t* bh = &bhi[nt >> 1][(nt & 1) * 2];
                    const uint32_t* bl = &blo[nt >> 1][(nt & 1) * 2];
                    mma16816(acc[mt][nt], ahi, bh);
                    mma16816(acc[mt][nt], ahi, bl);
                    mma16816(acc[mt][nt], alo, bh);
                }
            }
        }
        __syncthreads();
    }

    // ---- epilogue: Y in fp16 ----
    int group = lane >> 2, tig = lane & 3;
#pragma unroll
    for (int mt = 0; mt < 4; mt++) {
#pragma unroll
        for (int half = 0; half < 2; half++) {
            int row = m0 + warp_m * 64 + mt * 16 + group + half * 8;
            if (row < NN) {
#pragma unroll
                for (int nt = 0; nt < 4; nt++) {
                    int col = n0 + warp_n * 32 + nt * 8 + 2 * tig;
                    __half2 hv = __floats2half2_rn(acc[mt][nt][half * 2 + 0],
                                                   acc[mt][nt][half * 2 + 1]);
                    *(__half2*)(Y + (size_t)row * NOUT + col) = hv;
                }
            }
        }
    }
}

// ---------------- launch ----------------
extern "C" void kernel_launch(void* const* d_in, const int* in_sizes, int n_in,
                              void* d_out, int out_size) {
    const float* features = (const float*)d_in[0];
    const int*   etypes   = (const int*)d_in[1];
    const float* ew       = (const float*)d_in[2];
    const int*   src      = (const int*)d_in[3];
    const int*   dst      = (const int*)d_in[4];
    const float* comp1    = (const float*)d_in[5];
    const float* V1       = (const float*)d_in[6];
    const float* bias1    = (const float*)d_in[7];
    const float* comp2    = (const float*)d_in[8];
    const float* V2       = (const float*)d_in[9];
    const float* bias2    = (const float*)d_in[10];
    float* out = (float*)d_out;

    __half* Yp;
    float* hp;
    __nv_bfloat16 *Whi1, *Wlo1, *Whi2, *Wlo2;
    cudaGetSymbolAddress((void**)&Yp,   g_Y);
    cudaGetSymbolAddress((void**)&hp,   g_h);
    cudaGetSymbolAddress((void**)&Whi1, g_Whi1);
    cudaGetSymbolAddress((void**)&Wlo1, g_Wlo1);
    cudaGetSymbolAddress((void**)&Whi2, g_Whi2);
    cudaGetSymbolAddress((void**)&Wlo2, g_Wlo2);

    cudaFuncSetAttribute(gemm_y<false>, cudaFuncAttributeMaxDynamicSharedMemorySize, SM_TOT);
    cudaFuncSetAttribute(gemm_y<true>,  cudaFuncAttributeMaxDynamicSharedMemorySize, SM_TOT);

    compute_Wt<<<512, 256>>>(comp1, V1, Whi1, Wlo1);
    compute_Wt<<<512, 256>>>(comp2, V2, Whi2, Wlo2);

    dim3 ggrid((NN + 127) / 128, NR);   // 391 x 8
    const int SC_BLOCKS = (NE * 16 + 255) / 256;   // 50000

    // Layer 1: Y = X @ W1 ; h = bias1 + scatter(Y)
    gemm_y<false><<<ggrid, 256, SM_TOT>>>(features, Whi1, Wlo1, Yp);
    init_bias<<<NN * 32 / 256, 256>>>((float4*)hp, (const float4*)bias1);
    scatter_out<<<SC_BLOCKS, 256>>>((const uint4*)Yp, src, dst, etypes, ew, hp);

    // Layer 2: Y = relu(h) @ W2 ; out = bias2 + scatter(Y)
    gemm_y<true><<<ggrid, 256, SM_TOT>>>(hp, Whi2, Wlo2, Yp);
    init_bias<<<NN * 32 / 256, 256>>>((float4*)out, (const float4*)bias2);
    scatter_out<<<SC_BLOCKS, 256>>>((const uint4*)Yp, src, dst, etypes, ew, out);
}

// round 9
// speedup vs baseline: 3.4270x; 1.2660x over previous
#include <cuda_runtime.h>
#include <cuda_bf16.h>
#include <cuda_fp16.h>
#include <cstdint>

#define NN 50000
#define NE 800000
#define DIM 128
#define NR 8
#define NOUT (NR * DIM)   // 1024 = Y row length
#define NBLK 196          // scan blocks: 196*256 = 50176 >= NN

// ---------------- scratch (device globals: allocation-free) ----------------
__device__ __align__(16) __half g_Y[(size_t)NN * NOUT];    // 102.4 MB projected features (fp16)
__device__ float g_h[(size_t)NN * DIM];                    // layer-1 output (fp32)
__device__ __align__(16) __nv_bfloat16 g_Whi1[NOUT * DIM]; // Wt hi/lo, [n=r*128+o][k=i]
__device__ __align__(16) __nv_bfloat16 g_Wlo1[NOUT * DIM];
__device__ __align__(16) __nv_bfloat16 g_Whi2[NOUT * DIM];
__device__ __align__(16) __nv_bfloat16 g_Wlo2[NOUT * DIM];
// CSR-by-dst structures
__device__ int   g_cnt[NBLK * 256];        // zero-padded histogram
__device__ int   g_bsum[256];              // per-block sums (padded)
__device__ int   g_bpre[256];              // exclusive prefix of block sums
__device__ int   g_off[NBLK * 256 + 1];    // CSR offsets
__device__ int   g_pos[NBLK * 256];        // bump cursors
__device__ int   g_psr[NE];                // packed (etype<<24)|src, permuted
__device__ float g_pw[NE];                 // edge weight, permuted

__device__ __forceinline__ uint32_t smem_u32(const void* p) {
    uint32_t a;
    asm("{ .reg .u64 t; cvta.to.shared.u64 t, %1; cvt.u32.u64 %0, t; }" : "=r"(a) : "l"(p));
    return a;
}

// ---------------- W composition: Wt[n][k] split into bf16 hi/lo ----------------
__global__ void compute_Wt(const float* __restrict__ comp, const float* __restrict__ V,
                           __nv_bfloat16* __restrict__ Whi, __nv_bfloat16* __restrict__ Wlo) {
    int idx = blockIdx.x * blockDim.x + threadIdx.x;   // 131072
    int r = idx >> 14;
    int io = idx & 16383;
    int i = io >> 7;
    int o = io & 127;
    float acc = 0.f;
#pragma unroll
    for (int b = 0; b < NR; b++)
        acc += comp[r * NR + b] * V[b * 16384 + io];
    __nv_bfloat16 hi = __float2bfloat16(acc);
    __nv_bfloat16 lo = __float2bfloat16(acc - __bfloat162float(hi));
    int n = r * DIM + o;
    Whi[(size_t)n * DIM + i] = hi;
    Wlo[(size_t)n * DIM + i] = lo;
}

// ---------------- CSR build ----------------
__global__ void hist(const int* __restrict__ dst) {
    int e = blockIdx.x * blockDim.x + threadIdx.x;
    if (e < NE) atomicAdd(&g_cnt[dst[e]], 1);
}
// block sums of 256-bin chunks
__global__ void scan1() {
    __shared__ int s[256];
    int t = threadIdx.x;
    int v = g_cnt[blockIdx.x * 256 + t];
    s[t] = v; __syncthreads();
#pragma unroll
    for (int o = 1; o < 256; o <<= 1) {
        int x = (t >= o) ? s[t - o] : 0; __syncthreads();
        s[t] += x; __syncthreads();
    }
    if (t == 255) g_bsum[blockIdx.x] = s[255];
}
// exclusive prefix of NBLK block sums (single block)
__global__ void scan2() {
    __shared__ int s[256];
    int t = threadIdx.x;
    int v = (t < NBLK) ? g_bsum[t] : 0;
    s[t] = v; __syncthreads();
#pragma unroll
    for (int o = 1; o < 256; o <<= 1) {
        int x = (t >= o) ? s[t - o] : 0; __syncthreads();
        s[t] += x; __syncthreads();
    }
    if (t < NBLK) g_bpre[t] = s[t] - v;   // exclusive
}
// final offsets: off[i] = bpre[blk] + local exclusive scan; also off[last]=NE
__global__ void scan3() {
    __shared__ int s[256];
    int t = threadIdx.x;
    int i = blockIdx.x * 256 + t;
    int v = g_cnt[i];
    s[t] = v; __syncthreads();
#pragma unroll
    for (int o = 1; o < 256; o <<= 1) {
        int x = (t >= o) ? s[t - o] : 0; __syncthreads();
        s[t] += x; __syncthreads();
    }
    g_off[i] = g_bpre[blockIdx.x] + s[t] - v;
    if (i == NBLK * 256 - 1) g_off[NBLK * 256] = NE;
}
__global__ void permute(const int* __restrict__ src, const int* __restrict__ dst,
                        const int* __restrict__ et, const float* __restrict__ w) {
    int e = blockIdx.x * blockDim.x + threadIdx.x;
    if (e >= NE) return;
    int d = dst[e];
    int p = atomicAdd(&g_pos[d], 1);
    g_psr[p] = (et[e] << 24) | src[e];
    g_pw[p]  = w[e];
}

// ---------------- gather: one warp per node ----------------
// out[n, :] = bias + sum_{j in off[n]..off[n+1]} w_j * Y[src_j, rel_j, :]
__global__ void __launch_bounds__(256) gather(const __half* __restrict__ Y,
                                              const float* __restrict__ bias,
                                              float* __restrict__ out) {
    int wid = threadIdx.x >> 5, lane = threadIdx.x & 31;
    int n = blockIdx.x * 8 + wid;
    if (n >= NN) return;
    int beg = g_off[n], end = g_off[n + 1];
    float4 acc = *(const float4*)(bias + lane * 4);
    for (int j = beg; j < end; j++) {
        int sr   = g_psr[j];       // uniform within warp (broadcast)
        float we = g_pw[j];
        int s = sr & 0xFFFFFF;
        int r = sr >> 24;
        uint2 v = *(const uint2*)(Y + (size_t)s * NOUT + r * DIM + lane * 4);
        float2 f0 = __half22float2(*(const __half2*)&v.x);
        float2 f1 = __half22float2(*(const __half2*)&v.y);
        acc.x = fmaf(we, f0.x, acc.x);
        acc.y = fmaf(we, f0.y, acc.y);
        acc.z = fmaf(we, f1.x, acc.z);
        acc.w = fmaf(we, f1.y, acc.w);
    }
    *(float4*)(out + (size_t)n * DIM + lane * 4) = acc;
}

// ---------------- split-bf16 HMMA GEMM: Y = X @ Wt^T (fp16 out) ----------------
#define ASTR 144
#define SM_AHI 0
#define SM_ALO 18432
#define SM_BHI 36864
#define SM_BLO 55296
#define SM_TOT 73728

__device__ __forceinline__ void ldsm_x4(uint32_t* r, uint32_t addr) {
    asm volatile("ldmatrix.sync.aligned.m8n8.x4.shared.b16 {%0,%1,%2,%3}, [%4];"
                 : "=r"(r[0]), "=r"(r[1]), "=r"(r[2]), "=r"(r[3]) : "r"(addr));
}
__device__ __forceinline__ void mma16816(float* c, const uint32_t* a, const uint32_t* b) {
    asm volatile(
        "mma.sync.aligned.m16n8k16.row.col.f32.bf16.bf16.f32 "
        "{%0,%1,%2,%3}, {%4,%5,%6,%7}, {%8,%9}, {%0,%1,%2,%3};"
        : "+f"(c[0]), "+f"(c[1]), "+f"(c[2]), "+f"(c[3])
        : "r"(a[0]), "r"(a[1]), "r"(a[2]), "r"(a[3]), "r"(b[0]), "r"(b[1]));
}

template<bool RELU_A>
__global__ void __launch_bounds__(256, 2) gemm_y(const float* __restrict__ A,
                                                 const __nv_bfloat16* __restrict__ Bhi,
                                                 const __nv_bfloat16* __restrict__ Blo,
                                                 __half* __restrict__ Y) {
    extern __shared__ char dsm[];
    uint32_t sb = smem_u32(dsm);
    int t = threadIdx.x;
    int lane = t & 31, wid = t >> 5;
    int warp_m = wid >> 2, warp_n = wid & 3;
    int m0 = blockIdx.x * 128;
    int n0 = blockIdx.y * 128;

    float acc[4][4][4] = {};

    for (int kc = 0; kc < 2; kc++) {
#pragma unroll
        for (int j = 0; j < 8; j++) {
            int lin = t + j * 256;
            int l2 = lin & 1023;
            int row = l2 >> 3, q = l2 & 7;
            const __nv_bfloat16* srcp = (lin < 1024) ? Bhi : Blo;
            uint32_t db = sb + ((lin < 1024) ? SM_BHI : SM_BLO) + row * ASTR + q * 16;
            const void* gp = srcp + (size_t)(n0 + row) * DIM + kc * 64 + q * 8;
            asm volatile("cp.async.ca.shared.global [%0], [%1], 16;"
                         :: "r"(db), "l"(gp) : "memory");
        }
#pragma unroll
        for (int j = 0; j < 8; j++) {
            int lin = t + j * 256;
            int row = lin >> 4, q = lin & 15;
            float4 v = make_float4(0.f, 0.f, 0.f, 0.f);
            int gr = m0 + row;
            if (gr < NN) v = *(const float4*)(A + (size_t)gr * DIM + kc * 64 + q * 4);
            if (RELU_A) {
                v.x = fmaxf(v.x, 0.f); v.y = fmaxf(v.y, 0.f);
                v.z = fmaxf(v.z, 0.f); v.w = fmaxf(v.w, 0.f);
            }
            __nv_bfloat16 hx = __float2bfloat16(v.x), hy = __float2bfloat16(v.y);
            __nv_bfloat16 hz = __float2bfloat16(v.z), hw = __float2bfloat16(v.w);
            __nv_bfloat16 lx = __float2bfloat16(v.x - __bfloat162float(hx));
            __nv_bfloat16 ly = __float2bfloat16(v.y - __bfloat162float(hy));
            __nv_bfloat16 lz = __float2bfloat16(v.z - __bfloat162float(hz));
            __nv_bfloat16 lw = __float2bfloat16(v.w - __bfloat162float(hw));
            uint32_t h01 = (uint32_t)__bfloat16_as_ushort(hx) | ((uint32_t)__bfloat16_as_ushort(hy) << 16);
            uint32_t h23 = (uint32_t)__bfloat16_as_ushort(hz) | ((uint32_t)__bfloat16_as_ushort(hw) << 16);
            uint32_t l01 = (uint32_t)__bfloat16_as_ushort(lx) | ((uint32_t)__bfloat16_as_ushort(ly) << 16);
            uint32_t l23 = (uint32_t)__bfloat16_as_ushort(lz) | ((uint32_t)__bfloat16_as_ushort(lw) << 16);
            uint32_t off = row * ASTR + q * 8;
            asm volatile("st.shared.v2.b32 [%0], {%1,%2};"
                         :: "r"(sb + SM_AHI + off), "r"(h01), "r"(h23) : "memory");
            asm volatile("st.shared.v2.b32 [%0], {%1,%2};"
                         :: "r"(sb + SM_ALO + off), "r"(l01), "r"(l23) : "memory");
        }
        asm volatile("cp.async.commit_group;\n\tcp.async.wait_group 0;" ::: "memory");
        __syncthreads();

#pragma unroll
        for (int ks = 0; ks < 4; ks++) {
            uint32_t bhi[2][4], blo[2][4];
            int brow = warp_n * 32 + ((lane >> 4) & 1) * 8 + (lane & 7);
            uint32_t bcol = ks * 32 + ((lane >> 3) & 1) * 16;
#pragma unroll
            for (int pr = 0; pr < 2; pr++) {
                uint32_t boff = (brow + pr * 16) * ASTR + bcol;
                ldsm_x4(bhi[pr], sb + SM_BHI + boff);
                ldsm_x4(blo[pr], sb + SM_BLO + boff);
            }
#pragma unroll
            for (int mt = 0; mt < 4; mt++) {
                uint32_t ahi[4], alo[4];
                int arow = warp_m * 64 + mt * 16 + (lane & 15);
                uint32_t aoff = arow * ASTR + ks * 32 + (lane >> 4) * 16;
                ldsm_x4(ahi, sb + SM_AHI + aoff);
                ldsm_x4(alo, sb + SM_ALO + aoff);
#pragma unroll
                for (int nt = 0; nt < 4; nt++) {
                    const uint32_t* bh = &bhi[nt >> 1][(nt & 1) * 2];
                    const uint32_t* bl = &blo[nt >> 1][(nt & 1) * 2];
                    mma16816(acc[mt][nt], ahi, bh);
                    mma16816(acc[mt][nt], ahi, bl);
                    mma16816(acc[mt][nt], alo, bh);
                }
            }
        }
        __syncthreads();
    }

    int group = lane >> 2, tig = lane & 3;
#pragma unroll
    for (int mt = 0; mt < 4; mt++) {
#pragma unroll
        for (int half = 0; half < 2; half++) {
            int row = m0 + warp_m * 64 + mt * 16 + group + half * 8;
            if (row < NN) {
#pragma unroll
                for (int nt = 0; nt < 4; nt++) {
                    int col = n0 + warp_n * 32 + nt * 8 + 2 * tig;
                    __half2 hv = __floats2half2_rn(acc[mt][nt][half * 2 + 0],
                                                   acc[mt][nt][half * 2 + 1]);
                    *(__half2*)(Y + (size_t)row * NOUT + col) = hv;
                }
            }
        }
    }
}

// ---------------- launch ----------------
extern "C" void kernel_launch(void* const* d_in, const int* in_sizes, int n_in,
                              void* d_out, int out_size) {
    const float* features = (const float*)d_in[0];
    const int*   etypes   = (const int*)d_in[1];
    const float* ew       = (const float*)d_in[2];
    const int*   src      = (const int*)d_in[3];
    const int*   dst      = (const int*)d_in[4];
    const float* comp1    = (const float*)d_in[5];
    const float* V1       = (const float*)d_in[6];
    const float* bias1    = (const float*)d_in[7];
    const float* comp2    = (const float*)d_in[8];
    const float* V2       = (const float*)d_in[9];
    const float* bias2    = (const float*)d_in[10];
    float* out = (float*)d_out;

    __half* Yp;
    float* hp;
    __nv_bfloat16 *Whi1, *Wlo1, *Whi2, *Wlo2;
    int *cntp, *offp, *posp;
    cudaGetSymbolAddress((void**)&Yp,   g_Y);
    cudaGetSymbolAddress((void**)&hp,   g_h);
    cudaGetSymbolAddress((void**)&Whi1, g_Whi1);
    cudaGetSymbolAddress((void**)&Wlo1, g_Wlo1);
    cudaGetSymbolAddress((void**)&Whi2, g_Whi2);
    cudaGetSymbolAddress((void**)&Wlo2, g_Wlo2);
    cudaGetSymbolAddress((void**)&cntp, g_cnt);
    cudaGetSymbolAddress((void**)&offp, g_off);
    cudaGetSymbolAddress((void**)&posp, g_pos);

    cudaFuncSetAttribute(gemm_y<false>, cudaFuncAttributeMaxDynamicSharedMemorySize, SM_TOT);
    cudaFuncSetAttribute(gemm_y<true>,  cudaFuncAttributeMaxDynamicSharedMemorySize, SM_TOT);

    // Weights
    compute_Wt<<<512, 256>>>(comp1, V1, Whi1, Wlo1);
    compute_Wt<<<512, 256>>>(comp2, V2, Whi2, Wlo2);

    // CSR build (graph shared by both layers)
    cudaMemsetAsync(cntp, 0, NBLK * 256 * sizeof(int));
    hist<<<(NE + 255) / 256, 256>>>(dst);
    scan1<<<NBLK, 256>>>();
    scan2<<<1, 256>>>();
    scan3<<<NBLK, 256>>>();
    cudaMemcpyAsync(posp, offp, NBLK * 256 * sizeof(int), cudaMemcpyDeviceToDevice);
    permute<<<(NE + 255) / 256, 256>>>(src, dst, etypes, ew);

    dim3 ggrid((NN + 127) / 128, NR);   // 391 x 8
    const int GB = (NN + 7) / 8;        // 6250

    // Layer 1: Y = X @ W1 ; h = bias1 + gather(Y)
    gemm_y<false><<<ggrid, 256, SM_TOT>>>(features, Whi1, Wlo1, Yp);
    gather<<<GB, 256>>>(Yp, bias1, hp);

    // Layer 2: Y = relu(h) @ W2 ; out = bias2 + gather(Y)
    gemm_y<true><<<ggrid, 256, SM_TOT>>>(hp, Whi2, Wlo2, Yp);
    gather<<<GB, 256>>>(Yp, bias2, out);
}